// round 16
// baseline (speedup 1.0000x reference)
#include <cuda_runtime.h>
#include <math.h>

#define BATCH 8192
#define DIM   2048
#define WORDS 64                 // 2048 bits / 32 per row
#define FROWS 32                 // rows per forward block
#define NSEG  16                 // segments per row (4 words each)
#define FTH   (FROWS * NSEG)     // 512 threads: warp = segment, lane = row
#define FGRID (BATCH / FROWS)    // 256 forward blocks

// ---------------- device scratch (no allocations allowed) ----------------
__device__ float4             g_tab1[256 * 3];  // 8-step products of K matrices
__device__ float4             g_tab7[128 * 3];  // 7-step K prefixes (bits 0..6)
__device__ float              g_pi[4];
__device__ float              g_e[2][4];        // emission probs per obs
__device__ unsigned           g_packed[BATCH * WORDS];
__device__ unsigned long long g_acc;            // fixed-point (2^32) sum of logp
__device__ unsigned           g_done;           // block completion counter

// =================== K1: pack + fp32 precompute + reset ==================
__global__ void __launch_bounds__(256) prep_kernel(const int* __restrict__ y,
                                                   const float* __restrict__ T,
                                                   const float* __restrict__ E,
                                                   const float* __restrict__ S) {
    if (blockIdx.x < 2048) {
        // ---- ballot-pack: warp packs 1024 consecutive ints -> 32 words ----
        int warp_id = (blockIdx.x * 256 + threadIdx.x) >> 5;   // 0..16383
        int lane    = threadIdx.x & 31;
        const int* p = y + (size_t)warp_id * 1024;
        unsigned my = 0;
        #pragma unroll
        for (int r = 0; r < 32; r++) {
            int v = __ldcs(p + r * 32 + lane);                 // streaming, read-once
            unsigned b = __ballot_sync(0xFFFFFFFFu, v != 0);
            if (lane == r) my = b;
        }
        g_packed[warp_id * 32 + lane] = my;                    // coalesced 128B store
        return;
    }

    // ---- precompute block (blockIdx.x == 2048): tables in FP32 ----
    int tid = threadIdx.x;
    if (tid == 0) { g_acc = 0ull; g_done = 0u; }

    float W[3][3], e[2][3];
    #pragma unroll
    for (int i = 0; i < 3; i++) {
        float t0 = T[i * 3 + 0], t1 = T[i * 3 + 1], t2 = T[i * 3 + 2];
        float m = fmaxf(t0, fmaxf(t1, t2));
        float s0 = expf(t0 - m), s1 = expf(t1 - m), s2 = expf(t2 - m);
        float Z = s0 + s1 + s2;
        W[i][0] = s0 / Z; W[i][1] = s1 / Z; W[i][2] = s2 / Z;
        float a = E[i * 2 + 0], b = E[i * 2 + 1];
        float mm = fmaxf(a, b);
        float ea = expf(a - mm), eb = expf(b - mm);
        float Ze = ea + eb;
        e[0][i] = ea / Ze;      // P(obs=0 | state i)
        e[1][i] = eb / Ze;      // P(obs=1 | state i)
    }

    int byte = tid;             // 0..255
    float P[3][3];
    {
        int b0 = byte & 1;
        #pragma unroll
        for (int i = 0; i < 3; i++)
            #pragma unroll
            for (int j = 0; j < 3; j++) P[i][j] = e[b0][i] * W[i][j];
    }
    #pragma unroll
    for (int t = 1; t < 7; t++) {               // steps 1..6 -> 7-step prefix
        int bt = (byte >> t) & 1;
        float Q[3][3];
        #pragma unroll
        for (int i = 0; i < 3; i++)
            #pragma unroll
            for (int j = 0; j < 3; j++)
                Q[i][j] = P[i][0] * (e[bt][0] * W[0][j])
                        + P[i][1] * (e[bt][1] * W[1][j])
                        + P[i][2] * (e[bt][2] * W[2][j]);
        #pragma unroll
        for (int i = 0; i < 3; i++)
            #pragma unroll
            for (int j = 0; j < 3; j++) P[i][j] = Q[i][j];
    }
    if (byte < 128) {                           // 7-step prefix (bits 0..6 only)
        #pragma unroll
        for (int i = 0; i < 3; i++)
            g_tab7[byte * 3 + i] = make_float4(P[i][0], P[i][1], P[i][2], 0.f);
    }
    {                                           // 8th step -> tab1
        int b7 = (byte >> 7) & 1;
        float Q[3][3];
        #pragma unroll
        for (int i = 0; i < 3; i++)
            #pragma unroll
            for (int j = 0; j < 3; j++)
                Q[i][j] = P[i][0] * (e[b7][0] * W[0][j])
                        + P[i][1] * (e[b7][1] * W[1][j])
                        + P[i][2] * (e[b7][2] * W[2][j]);
        #pragma unroll
        for (int i = 0; i < 3; i++)
            g_tab1[byte * 3 + i] = make_float4(Q[i][0], Q[i][1], Q[i][2], 0.f);
    }

    if (tid == 0) {
        float s0 = S[0], s1 = S[1], s2 = S[2];
        float m = fmaxf(s0, fmaxf(s1, s2));
        float a = expf(s0 - m), b = expf(s1 - m), d = expf(s2 - m);
        float Z = a + b + d;
        g_pi[0] = a / Z; g_pi[1] = b / Z; g_pi[2] = d / Z; g_pi[3] = 0.f;
        #pragma unroll
        for (int j = 0; j < 3; j++) { g_e[0][j] = e[0][j]; g_e[1][j] = e[1][j]; }
    }
}

// =================== K2: 16-way segmented forward + fused finalize ========
#define MATMUL(r0, r1, r2)                                                   \
    do {                                                                     \
        float n00 = fmaf(m00, (r0).x, fmaf(m01, (r1).x, m02 * (r2).x));      \
        float n01 = fmaf(m00, (r0).y, fmaf(m01, (r1).y, m02 * (r2).y));      \
        float n02 = fmaf(m00, (r0).z, fmaf(m01, (r1).z, m02 * (r2).z));      \
        float n10 = fmaf(m10, (r0).x, fmaf(m11, (r1).x, m12 * (r2).x));      \
        float n11 = fmaf(m10, (r0).y, fmaf(m11, (r1).y, m12 * (r2).y));      \
        float n12 = fmaf(m10, (r0).z, fmaf(m11, (r1).z, m12 * (r2).z));      \
        float n20 = fmaf(m20, (r0).x, fmaf(m21, (r1).x, m22 * (r2).x));      \
        float n21 = fmaf(m20, (r0).y, fmaf(m21, (r1).y, m22 * (r2).y));      \
        float n22 = fmaf(m20, (r0).z, fmaf(m21, (r1).z, m22 * (r2).z));      \
        m00 = n00; m01 = n01; m02 = n02;                                     \
        m10 = n10; m11 = n11; m12 = n12;                                     \
        m20 = n20; m21 = n21; m22 = n22;                                     \
    } while (0)

#define MAM()                                                       \
    do {                                                            \
        m00 *= scp; m01 *= scp; m02 *= scp;                         \
        m10 *= scp; m11 *= scp; m12 *= scp;                         \
        m20 *= scp; m21 *= scp; m22 *= scp;                         \
        etot += ep;                                                 \
        float s_ = m00 + m01 + m02;                                 \
        unsigned eb_ = __float_as_uint(s_) >> 23;                   \
        ep  = (int)eb_ - 127;                                       \
        scp = __uint_as_float((254u - eb_) << 23);                  \
    } while (0)

#define MULVEC(r0, r1, r2)                                          \
    do {                                                            \
        float n0 = fmaf(v0, (r0).x, fmaf(v1, (r1).x, v2 * (r2).x)); \
        float n1 = fmaf(v0, (r0).y, fmaf(v1, (r1).y, v2 * (r2).y)); \
        float n2 = fmaf(v0, (r0).z, fmaf(v1, (r1).z, v2 * (r2).z)); \
        v0 = n0; v1 = n1; v2 = n2;                                  \
    } while (0)

#define VAM()                                                       \
    do {                                                            \
        v0 *= scp; v1 *= scp; v2 *= scp; etot += ep;                \
        float s_ = v0 + v1 + v2;                                    \
        unsigned eb_ = __float_as_uint(s_) >> 23;                   \
        ep  = (int)eb_ - 127;                                       \
        scp = __uint_as_float((254u - eb_) << 23);                  \
    } while (0)

__global__ void __launch_bounds__(FTH) forward_kernel(float* __restrict__ out) {
    __shared__ float4   t1[768];              // 12 KB table
    __shared__ float4   t7[384];              //  6 KB prefix table
    __shared__ unsigned sw[FROWS][WORDS + 1]; // stride 65 -> conflict-free
    __shared__ float    cmb[FROWS][151];      // 15 segs x (9 mat + etot), stride 151
    __shared__ float    s_pi[4];
    __shared__ float    s_e[2][4];

    int tid  = threadIdx.x;
    int lane = tid & 31;
    int wid  = tid >> 5;                      // segment 0..15

    #pragma unroll
    for (int i = tid; i < 768; i += FTH) t1[i] = g_tab1[i];
    for (int i = tid; i < 384; i += FTH) t7[i] = g_tab7[i];
    const unsigned* src = g_packed + (size_t)blockIdx.x * FROWS * WORDS;
    #pragma unroll
    for (int i = tid; i < FROWS * WORDS; i += FTH) sw[i >> 6][i & 63] = src[i];
    if (tid == 0) {
        s_pi[0] = g_pi[0]; s_pi[1] = g_pi[1]; s_pi[2] = g_pi[2]; s_pi[3] = 0.f;
        #pragma unroll
        for (int j = 0; j < 3; j++) { s_e[0][j] = g_e[0][j]; s_e[1][j] = g_e[1][j]; }
    }
    __syncthreads();

    int row = lane, seg = wid;
    unsigned wds[4];
    #pragma unroll
    for (int k = 0; k < 4; k++) wds[k] = sw[row][seg * 4 + k];

    int   etot = 0, ep = 0;
    float scp = 1.0f;

    if (seg == 0) {
        float v0 = s_pi[0], v1 = s_pi[1], v2 = s_pi[2];
        #pragma unroll
        for (int k = 0; k < 4; k++) {
            unsigned w = wds[k];
            unsigned b0 = w & 255u, b1 = (w >> 8) & 255u;
            unsigned b2 = (w >> 16) & 255u, b3 = w >> 24;
            MULVEC(t1[b0 * 3], t1[b0 * 3 + 1], t1[b0 * 3 + 2]);
            MULVEC(t1[b1 * 3], t1[b1 * 3 + 1], t1[b1 * 3 + 2]);
            VAM();
            MULVEC(t1[b2 * 3], t1[b2 * 3 + 1], t1[b2 * 3 + 2]);
            MULVEC(t1[b3 * 3], t1[b3 * 3 + 1], t1[b3 * 3 + 2]);
            VAM();
        }
        __syncthreads();                       // wait for matrix segments

        // combine: v <- v * M1 * ... * M15 with exponent tracking
        #pragma unroll 1
        for (int s = 0; s < NSEG - 1; s++) {
            const float* M = &cmb[row][s * 10];
            float n0 = fmaf(v0, M[0], fmaf(v1, M[3], v2 * M[6]));
            float n1 = fmaf(v0, M[1], fmaf(v1, M[4], v2 * M[7]));
            float n2 = fmaf(v0, M[2], fmaf(v1, M[5], v2 * M[8]));
            etot += __float_as_int(M[9]);
            float s_ = n0 + n1 + n2;
            unsigned eb = __float_as_uint(s_) >> 23;
            etot += (int)eb - 127;
            float sc = __uint_as_float((254u - eb) << 23);
            v0 = n0 * sc; v1 = n1 * sc; v2 = n2 * sc;
        }
        float logp = logf(v0 + v1 + v2) + (float)etot * 0.69314718055994530942f;

        // warp reduce over 32 rows, deterministic fixed-point atomic
        double d = (double)logp;
        #pragma unroll
        for (int off = 16; off > 0; off >>= 1)
            d += __shfl_down_sync(0xFFFFFFFFu, d, off);

        if (lane == 0) {
            long long fx = __double2ll_rn(d * 4294967296.0);     // 2^32 fixed point
            atomicAdd(&g_acc, (unsigned long long)fx);           // exact, associative
            __threadfence();
            unsigned prev = atomicAdd(&g_done, 1u);
            if (prev == FGRID - 1) {
                unsigned long long a = atomicAdd(&g_acc, 0ull);  // ordered read
                double tot = (double)(long long)a * (1.0 / 4294967296.0);
                out[0] = (float)(tot / (double)BATCH);
            }
        }
    } else {
        float m00 = 1.f, m01 = 0.f, m02 = 0.f;
        float m10 = 0.f, m11 = 1.f, m12 = 0.f;
        float m20 = 0.f, m21 = 0.f, m22 = 1.f;
        #pragma unroll
        for (int k = 0; k < 3; k++) {
            unsigned w = wds[k];
            unsigned b0 = w & 255u, b1 = (w >> 8) & 255u;
            unsigned b2 = (w >> 16) & 255u, b3 = w >> 24;
            MATMUL(t1[b0 * 3], t1[b0 * 3 + 1], t1[b0 * 3 + 2]);
            MATMUL(t1[b1 * 3], t1[b1 * 3 + 1], t1[b1 * 3 + 2]);
            MAM();
            MATMUL(t1[b2 * 3], t1[b2 * 3 + 1], t1[b2 * 3 + 2]);
            MATMUL(t1[b3 * 3], t1[b3 * 3 + 1], t1[b3 * 3 + 2]);
            MAM();
        }
        {   // last word of this segment
            unsigned w = wds[3];
            unsigned b0 = w & 255u, b1 = (w >> 8) & 255u;
            unsigned b2 = (w >> 16) & 255u, b3 = w >> 24;
            MATMUL(t1[b0 * 3], t1[b0 * 3 + 1], t1[b0 * 3 + 2]);
            MATMUL(t1[b1 * 3], t1[b1 * 3 + 1], t1[b1 * 3 + 2]);
            MAM();
            MATMUL(t1[b2 * 3], t1[b2 * 3 + 1], t1[b2 * 3 + 2]);
            if (seg == NSEG - 1) {
                // final byte of the row: 7-step prefix, columns scaled by e[b7]
                unsigned idx = b3 & 127u, sel = b3 >> 7;
                MATMUL(t7[idx * 3], t7[idx * 3 + 1], t7[idx * 3 + 2]);
                float c0 = s_e[sel][0], c1 = s_e[sel][1], c2 = s_e[sel][2];
                m00 *= c0; m01 *= c1; m02 *= c2;
                m10 *= c0; m11 *= c1; m12 *= c2;
                m20 *= c0; m21 *= c1; m22 *= c2;
            } else {
                MATMUL(t1[b3 * 3], t1[b3 * 3 + 1], t1[b3 * 3 + 2]);
            }
            MAM();
        }
        float* c = &cmb[row][(seg - 1) * 10];
        c[0] = m00; c[1] = m01; c[2] = m02;
        c[3] = m10; c[4] = m11; c[5] = m12;
        c[6] = m20; c[7] = m21; c[8] = m22;
        c[9] = __int_as_float(etot);          // pending (scp,ep) is exact identity
        __syncthreads();                      // release seg0 combine
    }
}

// ---------------- launch: 2 graph nodes ----------------
extern "C" void kernel_launch(void* const* d_in, const int* in_sizes, int n_in,
                              void* d_out, int out_size) {
    const int*   y = (const int*)d_in[0];
    const float* T = (const float*)d_in[1];
    const float* E = (const float*)d_in[2];
    const float* S = (const float*)d_in[3];

    prep_kernel<<<2049, 256>>>(y, T, E, S);   // 2048 pack blocks + 1 fp32 precompute
    forward_kernel<<<FGRID, FTH>>>((float*)d_out);
}